// round 3
// baseline (speedup 1.0000x reference)
#include <cuda_runtime.h>
#include <cstdint>
#include <math.h>

// Problem dims (fixed by the dataset)
#define M_TOK 8192   // B*S
#define HID   2048   // hidden
#define INTER 8192   // intermediate

// ---------------- scratch (allocation-free rule: __device__ globals) --------
__device__ float g_y[(size_t)M_TOK * HID];     // LN output, tf32-rounded   (64 MB)
__device__ float g_z[(size_t)M_TOK * INTER];   // GeGLU output, tf32-rounded (256 MB)

// ---------------- helpers ---------------------------------------------------
__device__ __forceinline__ uint32_t tf32_bits(float x) {
    uint32_t u;
    asm("cvt.rna.tf32.f32 %0, %1;" : "=r"(u) : "f"(x));
    return u;
}
__device__ __forceinline__ float to_tf32(float x) {
    return __uint_as_float(tf32_bits(x));
}
__device__ __forceinline__ void cp16(uint32_t dst_smem, const void* src) {
    asm volatile("cp.async.cg.shared.global [%0], [%1], 16;\n" ::"r"(dst_smem), "l"(src));
}
__device__ __forceinline__ void cp_commit() {
    asm volatile("cp.async.commit_group;\n");
}
__device__ __forceinline__ void mma_tf32(float* c, const uint32_t* a, const uint32_t* b) {
    asm volatile(
        "mma.sync.aligned.m16n8k8.row.col.f32.tf32.tf32.f32 "
        "{%0,%1,%2,%3}, {%4,%5,%6,%7}, {%8,%9}, {%0,%1,%2,%3};\n"
        : "+f"(c[0]), "+f"(c[1]), "+f"(c[2]), "+f"(c[3])
        : "r"(a[0]), "r"(a[1]), "r"(a[2]), "r"(a[3]), "r"(b[0]), "r"(b[1]));
}

// ---------------- LayerNorm -------------------------------------------------
// One block per token row. H=2048, 256 threads, 2 float4 per thread.
__global__ void ln_kernel(const float* __restrict__ x,
                          const float* __restrict__ scale,
                          const float* __restrict__ bias) {
    const int row = blockIdx.x;
    const float4* xr = reinterpret_cast<const float4*>(x + (size_t)row * HID);
    float4 v[2];
    v[0] = xr[threadIdx.x];
    v[1] = xr[threadIdx.x + 256];

    float s = 0.f, ss = 0.f;
#pragma unroll
    for (int i = 0; i < 2; i++) {
        s += v[i].x + v[i].y + v[i].z + v[i].w;
        ss += v[i].x * v[i].x + v[i].y * v[i].y + v[i].z * v[i].z + v[i].w * v[i].w;
    }
#pragma unroll
    for (int o = 16; o; o >>= 1) {
        s += __shfl_xor_sync(0xFFFFFFFFu, s, o);
        ss += __shfl_xor_sync(0xFFFFFFFFu, ss, o);
    }
    __shared__ float rs[8], rss[8];
    const int w = threadIdx.x >> 5, l = threadIdx.x & 31;
    if (l == 0) { rs[w] = s; rss[w] = ss; }
    __syncthreads();
    if (threadIdx.x == 0) {
        float S = 0.f, SS = 0.f;
#pragma unroll
        for (int i = 0; i < 8; i++) { S += rs[i]; SS += rss[i]; }
        rs[0] = S; rss[0] = SS;
    }
    __syncthreads();
    const float mean = rs[0] * (1.0f / HID);
    const float var  = rss[0] * (1.0f / HID) - mean * mean;
    const float rstd = rsqrtf(var + 1e-6f);

    float4* yr = reinterpret_cast<float4*>(g_y + (size_t)row * HID);
    const float4* sc4 = reinterpret_cast<const float4*>(scale);
    const float4* b4  = reinterpret_cast<const float4*>(bias);
#pragma unroll
    for (int i = 0; i < 2; i++) {
        const int c = threadIdx.x + i * 256;
        float4 sv = sc4[c], bv = b4[c], xv = v[i], o;
        o.x = to_tf32((xv.x - mean) * rstd * sv.x + bv.x);
        o.y = to_tf32((xv.y - mean) * rstd * sv.y + bv.y);
        o.z = to_tf32((xv.z - mean) * rstd * sv.z + bv.z);
        o.w = to_tf32((xv.w - mean) * rstd * sv.w + bv.w);
        yr[c] = o;
    }
}

// ---------------- tiled tf32 GEMM ------------------------------------------
// BM=128, BN=128, BK=16, 256 threads (8 warps as 2x4), warp tile 64x32,
// 4-stage cp.async pipeline.
// GEGLU=true : A=g_y [M,2048], B=W1 [2048, 2*I] with interleaved-halves N-tile
//              (tile cols 0..63 -> branch0 i0..i0+63, cols 64..127 -> branch1),
//              epilogue computes gelu(h0)*h1 -> g_z (tf32-rounded).
// GEGLU=false: A=g_z [M,8192], B=W2 [8192,2048], plain fp32 epilogue -> out.
constexpr int BM = 128, BN = 128, BK = 16;
constexpr int STAGES = 4;
constexpr int ASTRIDE = BK + 4;           // 20 floats (80B, 16B aligned, conflict-free frags)
constexpr int BSTRIDE = BN + 4;           // 132 floats (528B, 16B aligned)
constexpr int A_STAGE = BM * ASTRIDE;     // 2560 floats
constexpr int B_STAGE = BK * BSTRIDE;     // 2112 floats
constexpr int SMEM_FLOATS = STAGES * (A_STAGE + B_STAGE);  // 18688 -> 74752 B

template <bool GEGLU>
__global__ __launch_bounds__(256) void gemm_tf32(const float* __restrict__ Bw,
                                                 float* __restrict__ OutP,
                                                 int Kdim, int ldb) {
    extern __shared__ float smem[];
    const float* A = GEGLU ? g_y : g_z;

    const int tid = threadIdx.x;
    const int m0 = blockIdx.y * BM;
    const int i0 = blockIdx.x * 64;   // GEGLU: i-range of this CTA
    const int n0 = blockIdx.x * BN;   // plain: output-col range

    // ---- loader setup (2x 16B chunks for A, 2x for B, per thread) ----
    const int arow0 = tid >> 2;
    const int arow1 = arow0 + 64;
    const int acol  = (tid & 3) * 4;
    const float* aSrc0 = A + (size_t)(m0 + arow0) * Kdim + acol;
    const float* aSrc1 = A + (size_t)(m0 + arow1) * Kdim + acol;

    const int brow0 = tid >> 5;       // 0..7
    const int brow1 = brow0 + 8;      // 8..15
    const int j00   = (tid & 31) * 4; // tile col 0..124
    int gcol;
    if (GEGLU) gcol = (j00 < 64) ? (i0 + j00) : (INTER + i0 + (j00 - 64));
    else       gcol = n0 + j00;
    const float* bSrc0 = Bw + (size_t)brow0 * ldb + gcol;
    const float* bSrc1 = Bw + (size_t)brow1 * ldb + gcol;

    const uint32_t sbase = (uint32_t)__cvta_generic_to_shared(smem);
    const uint32_t aOff0 = (arow0 * ASTRIDE + acol) * 4;
    const uint32_t aOff1 = (arow1 * ASTRIDE + acol) * 4;
    const uint32_t bBase = STAGES * A_STAGE * 4;
    const uint32_t bOff0 = bBase + (brow0 * BSTRIDE + j00) * 4;
    const uint32_t bOff1 = bBase + (brow1 * BSTRIDE + j00) * 4;

    auto load_stage = [&](int kt, int s) {
        const uint32_t sa = sbase + s * (A_STAGE * 4);
        const uint32_t sb = sbase + s * (B_STAGE * 4);
        cp16(sa + aOff0, aSrc0 + (size_t)kt * BK);
        cp16(sa + aOff1, aSrc1 + (size_t)kt * BK);
        cp16(sb + bOff0, bSrc0 + (size_t)kt * BK * ldb);
        cp16(sb + bOff1, bSrc1 + (size_t)kt * BK * ldb);
    };

    const int kIters = Kdim / BK;
#pragma unroll
    for (int s = 0; s < STAGES - 1; s++) { load_stage(s, s); cp_commit(); }

    const int warp = tid >> 5, lane = tid & 31;
    const int wm = warp >> 2, wn = warp & 3;   // 2 x 4 warps
    const int g = lane >> 2, t = lane & 3;

    float acc[4][4][4];
#pragma unroll
    for (int a = 0; a < 4; a++)
#pragma unroll
        for (int b = 0; b < 4; b++)
#pragma unroll
            for (int c = 0; c < 4; c++) acc[a][b][c] = 0.f;

    for (int kt = 0; kt < kIters; kt++) {
        const int s = kt & (STAGES - 1);
        asm volatile("cp.async.wait_group %0;\n" ::"n"(STAGES - 2));
        __syncthreads();
        const int nk = kt + STAGES - 1;
        if (nk < kIters) load_stage(nk, nk & (STAGES - 1));
        cp_commit();

        const float* As_ = smem + s * A_STAGE;
        const float* Bs_ = smem + STAGES * A_STAGE + s * B_STAGE;
#pragma unroll
        for (int ks = 0; ks < 2; ks++) {
            uint32_t af[4][4], bf[4][2];
#pragma unroll
            for (int mt = 0; mt < 4; mt++) {
                const int r = wm * 64 + mt * 16 + g;
                const int c = ks * 8 + t;
                af[mt][0] = __float_as_uint(As_[r * ASTRIDE + c]);
                af[mt][1] = __float_as_uint(As_[(r + 8) * ASTRIDE + c]);
                af[mt][2] = __float_as_uint(As_[r * ASTRIDE + c + 4]);
                af[mt][3] = __float_as_uint(As_[(r + 8) * ASTRIDE + c + 4]);
            }
#pragma unroll
            for (int nt = 0; nt < 4; nt++) {
                const int cc = wn * 32 + nt * 8 + g;
                const int rr = ks * 8 + t;
                bf[nt][0] = tf32_bits(Bs_[rr * BSTRIDE + cc]);
                bf[nt][1] = tf32_bits(Bs_[(rr + 4) * BSTRIDE + cc]);
            }
#pragma unroll
            for (int mt = 0; mt < 4; mt++)
#pragma unroll
                for (int nt = 0; nt < 4; nt++)
                    mma_tf32(acc[mt][nt], af[mt], bf[nt]);
        }
    }

    if (!GEGLU) {
        // plain epilogue: fp32 out, [M, HID]
#pragma unroll
        for (int mt = 0; mt < 4; mt++)
#pragma unroll
            for (int nt = 0; nt < 4; nt++) {
                const int r = m0 + wm * 64 + mt * 16 + g;
                const int c = n0 + wn * 32 + nt * 8 + 2 * t;
                float2 v0 = make_float2(acc[mt][nt][0], acc[mt][nt][1]);
                float2 v1 = make_float2(acc[mt][nt][2], acc[mt][nt][3]);
                *reinterpret_cast<float2*>(OutP + (size_t)r * HID + c) = v0;
                *reinterpret_cast<float2*>(OutP + (size_t)(r + 8) * HID + c) = v1;
            }
    } else {
        // GeGLU epilogue: stage through smem, pair cols c (branch0) with c+64 (branch1)
        asm volatile("cp.async.wait_group 0;\n");
        __syncthreads();
        float* Cs = smem;  // 128 x BSTRIDE, fits in pipeline smem
#pragma unroll
        for (int mt = 0; mt < 4; mt++)
#pragma unroll
            for (int nt = 0; nt < 4; nt++) {
                const int r = wm * 64 + mt * 16 + g;
                const int c = wn * 32 + nt * 8 + 2 * t;
                Cs[r * BSTRIDE + c]           = acc[mt][nt][0];
                Cs[r * BSTRIDE + c + 1]       = acc[mt][nt][1];
                Cs[(r + 8) * BSTRIDE + c]     = acc[mt][nt][2];
                Cs[(r + 8) * BSTRIDE + c + 1] = acc[mt][nt][3];
            }
        __syncthreads();
        for (int idx = tid; idx < 128 * 64; idx += 256) {
            const int r = idx >> 6, c = idx & 63;
            const float h0 = Cs[r * BSTRIDE + c];
            const float h1 = Cs[r * BSTRIDE + 64 + c];
            const float gl = 0.5f * h0 *
                (1.0f + tanhf(0.7978845608028654f * (h0 + 0.044715f * h0 * h0 * h0)));
            g_z[(size_t)(m0 + r) * INTER + i0 + c] = to_tf32(gl * h1);
        }
    }
}

// ---------------- launch ----------------------------------------------------
extern "C" void kernel_launch(void* const* d_in, const int* in_sizes, int n_in,
                              void* d_out, int out_size) {
    (void)in_sizes; (void)n_in; (void)out_size;
    const float* x     = (const float*)d_in[0];
    const float* scale = (const float*)d_in[1];
    const float* bias  = (const float*)d_in[2];
    const float* w1    = (const float*)d_in[3];  // [H, 2, I] row-major == [H, 2*I]
    const float* w2    = (const float*)d_in[4];  // [I, H]
    float* out = (float*)d_out;

    const size_t smem_bytes = (size_t)SMEM_FLOATS * sizeof(float);
    cudaFuncSetAttribute(gemm_tf32<true>,  cudaFuncAttributeMaxDynamicSharedMemorySize, (int)smem_bytes);
    cudaFuncSetAttribute(gemm_tf32<false>, cudaFuncAttributeMaxDynamicSharedMemorySize, (int)smem_bytes);

    ln_kernel<<<M_TOK, 256>>>(x, scale, bias);
    gemm_tf32<true><<<dim3(INTER / 64, M_TOK / BM), 256, smem_bytes>>>(w1, nullptr, HID, 2 * INTER);
    gemm_tf32<false><<<dim3(HID / BN, M_TOK / BM), 256, smem_bytes>>>(w2, out, INTER, HID);
}